// round 1
// baseline (speedup 1.0000x reference)
#include <cuda_runtime.h>
#include <cuda_bf16.h>

// Problem constants
#define Bc    4
#define Tc    2048
#define DINc  2048
#define Hc    2048
#define Ec    8
#define RANKc 64
#define NANCH 512            // T/NGRAM, T%NGRAM==0
#define SCALING 0.25f        // ALPHA/RANK = 16/64

// ---------------------------------------------------------------------------
// Scratch (no allocations allowed) 
// ---------------------------------------------------------------------------
__device__ float g_scale;
__device__ __align__(16) float g_pmix[Bc * NANCH * RANKc];

// ---------------------------------------------------------------------------
// Kernel 1: base = x @ W^T + b   (M=8192, N=2048, K=2048, fp32)
// 128x128 block tile, BK=8, 8x8 per thread, 256 threads.
// ---------------------------------------------------------------------------
__global__ __launch_bounds__(256) void sgemm_kernel(
    const float* __restrict__ A,     // [M, K]
    const float* __restrict__ Bw,    // [N, K]
    const float* __restrict__ bias,  // [N]
    float* __restrict__ C)           // [M, N]
{
    constexpr int M = Bc * Tc;
    constexpr int N = Hc;
    constexpr int K = DINc;

    __shared__ float As[8][128];
    __shared__ float Bs[8][128];

    const int tid  = threadIdx.x;
    const int bx   = blockIdx.x;      // N tile
    const int by   = blockIdx.y;      // M tile
    const int tx   = tid & 15;        // 16 thread cols
    const int ty   = tid >> 4;        // 16 thread rows
    const int lrow = tid >> 1;        // 0..127
    const int lcol = (tid & 1) << 2;  // 0 or 4

    const float* Ab = A  + (size_t)(by * 128 + lrow) * K + lcol;
    const float* Bb = Bw + (size_t)(bx * 128 + lrow) * K + lcol;

    float acc[8][8] = {};

    for (int k0 = 0; k0 < K; k0 += 8) {
        float4 a4 = *(const float4*)(Ab + k0);
        float4 b4 = *(const float4*)(Bb + k0);
        As[lcol + 0][lrow] = a4.x;
        As[lcol + 1][lrow] = a4.y;
        As[lcol + 2][lrow] = a4.z;
        As[lcol + 3][lrow] = a4.w;
        Bs[lcol + 0][lrow] = b4.x;
        Bs[lcol + 1][lrow] = b4.y;
        Bs[lcol + 2][lrow] = b4.z;
        Bs[lcol + 3][lrow] = b4.w;
        __syncthreads();

        #pragma unroll
        for (int k = 0; k < 8; k++) {
            float4 a0 = *(const float4*)&As[k][ty * 8];
            float4 a1 = *(const float4*)&As[k][ty * 8 + 4];
            float4 b0 = *(const float4*)&Bs[k][tx * 8];
            float4 b1 = *(const float4*)&Bs[k][tx * 8 + 4];
            float ar[8] = {a0.x, a0.y, a0.z, a0.w, a1.x, a1.y, a1.z, a1.w};
            float br[8] = {b0.x, b0.y, b0.z, b0.w, b1.x, b1.y, b1.z, b1.w};
            #pragma unroll
            for (int i = 0; i < 8; i++)
                #pragma unroll
                for (int j = 0; j < 8; j++)
                    acc[i][j] += ar[i] * br[j];
        }
        __syncthreads();
    }

    const int crow0 = by * 128 + ty * 8;
    const int ccol0 = bx * 128 + tx * 8;
    float bv[8];
    #pragma unroll
    for (int j = 0; j < 8; j++) bv[j] = bias[ccol0 + j];

    #pragma unroll
    for (int i = 0; i < 8; i++) {
        float* cp = C + (size_t)(crow0 + i) * N + ccol0;
        float4 v0, v1;
        v0.x = acc[i][0] + bv[0]; v0.y = acc[i][1] + bv[1];
        v0.z = acc[i][2] + bv[2]; v0.w = acc[i][3] + bv[3];
        v1.x = acc[i][4] + bv[4]; v1.y = acc[i][5] + bv[5];
        v1.z = acc[i][6] + bv[6]; v1.w = acc[i][7] + bv[7];
        *(float4*)(cp)     = v0;
        *(float4*)(cp + 4) = v1;
    }
}

// ---------------------------------------------------------------------------
// Kernel 2: global abs-max over Hs = base[:, anchors, :E]  (16384 values)
// Single block -> deterministic, no atomics, writes g_scale.
// ---------------------------------------------------------------------------
__global__ __launch_bounds__(256) void absmax_kernel(const float* __restrict__ C)
{
    __shared__ float red[256];
    float m = 0.0f;
    for (int i = threadIdx.x; i < Bc * NANCH * Ec; i += 256) {
        int b    = i >> 12;        // / (NANCH*Ec)=4096
        int rest = i & 4095;
        int a    = rest >> 3;
        int e    = rest & 7;
        int t    = a * 4 + 3;      // anchor index
        float v  = C[((size_t)(b * Tc + t)) * Hc + e];
        m = fmaxf(m, fabsf(v));
    }
    red[threadIdx.x] = m;
    __syncthreads();
    for (int s = 128; s > 0; s >>= 1) {
        if (threadIdx.x < s)
            red[threadIdx.x] = fmaxf(red[threadIdx.x], red[threadIdx.x + s]);
        __syncthreads();
    }
    if (threadIdx.x == 0) g_scale = fmaxf(red[0], 1e-6f);
}

// ---------------------------------------------------------------------------
// Kernel 3: per-anchor softmax / top-2 soft mask / w @ LiMEs -> g_pmix
// One thread per anchor (2048 anchors).
// ---------------------------------------------------------------------------
__global__ __launch_bounds__(256) void pmix_kernel(
    const float* __restrict__ C, const float* __restrict__ L)
{
    __shared__ float sL[Ec * RANKc];
    for (int i = threadIdx.x; i < Ec * RANKc; i += 256) sL[i] = L[i];
    __syncthreads();

    int idx = blockIdx.x * 256 + threadIdx.x;   // 0..2047
    int b   = idx >> 9;                          // / NANCH
    int a   = idx & (NANCH - 1);
    int t   = a * 4 + 3;
    const float* h = C + ((size_t)(b * Tc + t)) * Hc;

    float inv_scale = 1.0f / g_scale;            // TEMP = 1

    float l[Ec], lmax = -1e30f;
    #pragma unroll
    for (int e = 0; e < Ec; e++) {
        l[e] = h[e] * inv_scale;
        lmax = fmaxf(lmax, l[e]);
    }
    float p[Ec], s = 0.0f;
    #pragma unroll
    for (int e = 0; e < Ec; e++) { p[e] = expf(l[e] - lmax); s += p[e]; }
    float invs = 1.0f / s;
    #pragma unroll
    for (int e = 0; e < Ec; e++) p[e] *= invs;

    // top-2: m2 = 2nd largest = threshold
    float m1 = -1e30f, m2 = -1e30f;
    #pragma unroll
    for (int e = 0; e < Ec; e++) {
        float v = p[e];
        if (v > m1) { m2 = m1; m1 = v; }
        else if (v > m2) { m2 = v; }
    }
    // mask = sigmoid((p - thr)/SOFT_T), SOFT_T = 0.5
    float w[Ec], ws = 0.0f;
    #pragma unroll
    for (int e = 0; e < Ec; e++) {
        float mask = 1.0f / (1.0f + expf(-(p[e] - m2) * 2.0f));
        w[e] = p[e] * mask;
        ws  += w[e];
    }
    float invws = 1.0f / (ws + 1e-9f);

    float* out = g_pmix + (size_t)idx * RANKc;
    #pragma unroll 8
    for (int r = 0; r < RANKc; r++) {
        float acc = 0.0f;
        #pragma unroll
        for (int e = 0; e < Ec; e++) acc += w[e] * sL[e * RANKc + r];
        out[r] = acc * invws;
    }
}

// ---------------------------------------------------------------------------
// Kernel 4: out[..., :RANK] *= (1 + SCALING * p_mix_full)
// float4 per thread: B*T*16 = 131072 threads.
// ---------------------------------------------------------------------------
__global__ __launch_bounds__(256) void apply_kernel(float* __restrict__ C)
{
    int idx = blockIdx.x * blockDim.x + threadIdx.x;  // 0 .. B*T*16-1
    int r4  = idx & 15;
    int tg  = idx >> 4;                                // 0..8191 (b*T + t)
    int t   = tg & (Tc - 1);
    int b   = tg >> 11;
    int a   = t >> 2;

    const float4 p = ((const float4*)g_pmix)[((b << 9) + a) * 16 + r4];
    float4* cp = (float4*)(C + (size_t)tg * Hc) + r4;
    float4 v = *cp;
    v.x *= 1.0f + SCALING * p.x;
    v.y *= 1.0f + SCALING * p.y;
    v.z *= 1.0f + SCALING * p.z;
    v.w *= 1.0f + SCALING * p.w;
    *cp = v;
}

// ---------------------------------------------------------------------------
extern "C" void kernel_launch(void* const* d_in, const int* in_sizes, int n_in,
                              void* d_out, int out_size)
{
    const float* x = (const float*)d_in[0];   // [B, T, DIN]
    const float* W = (const float*)d_in[1];   // [H, DIN]
    const float* b = (const float*)d_in[2];   // [H]
    const float* L = (const float*)d_in[3];   // [E, RANK]
    float* out = (float*)d_out;               // [B, T, H]

    dim3 grid(Hc / 128, (Bc * Tc) / 128);     // (16, 64)
    sgemm_kernel<<<grid, 256>>>(x, W, b, out);
    absmax_kernel<<<1, 256>>>(out);
    pmix_kernel<<<(Bc * NANCH) / 256, 256>>>(out, L);
    apply_kernel<<<(Bc * Tc * 16) / 256, 256>>>(out);
}

// round 3
// speedup vs baseline: 2.5203x; 2.5203x over previous
#include <cuda_runtime.h>
#include <cuda_bf16.h>
#include <cstdint>

// Problem constants
#define Bc    4
#define Tc    2048
#define DINc  2048
#define Hc    2048
#define Ec    8
#define RANKc 64
#define NANCH 512
#define SCALING 0.25f

// GEMM tiling
#define TM 128
#define TN 128
#define KCF 64                    // fp32 K per chunk (= 64 bf16 = 128B rows)
#define NCHUNK (DINc / KCF)       // 32
#define TILE_B  16384             // one 128x64 bf16 tile (128 rows x 128B)
#define STAGE_B (4 * TILE_B)      // A_hi, A_lo, B_hi, B_lo
#define SMEM_TOTAL (2 * STAGE_B)  // 131072

__device__ float g_scale;
__device__ __align__(16) float g_pmix[Bc * NANCH * RANKc];

// ---------------------------------------------------------------------------
// Helpers
// ---------------------------------------------------------------------------
__device__ __forceinline__ uint32_t smem_u32(const void* p) {
    uint32_t a;
    asm("{ .reg .u64 t; cvta.to.shared.u64 t, %1; cvt.u32.u64 %0, t; }" : "=r"(a) : "l"(p));
    return a;
}
__device__ __forceinline__ uint32_t sw128(uint32_t off) { return off ^ ((off >> 3) & 0x70); }

__device__ __forceinline__ void ldmx4(uint32_t* r, uint32_t addr) {
    asm volatile("ldmatrix.sync.aligned.m8n8.x4.shared.b16 {%0,%1,%2,%3}, [%4];"
                 : "=r"(r[0]), "=r"(r[1]), "=r"(r[2]), "=r"(r[3]) : "r"(addr));
}
__device__ __forceinline__ void mma_bf16(float* c, const uint32_t* a, uint32_t b0, uint32_t b1) {
    asm volatile(
        "mma.sync.aligned.m16n8k16.row.col.f32.bf16.bf16.f32 "
        "{%0,%1,%2,%3},{%4,%5,%6,%7},{%8,%9},{%0,%1,%2,%3};"
        : "+f"(c[0]), "+f"(c[1]), "+f"(c[2]), "+f"(c[3])
        : "r"(a[0]), "r"(a[1]), "r"(a[2]), "r"(a[3]), "r"(b0), "r"(b1));
}
__device__ __forceinline__ void split4(float4 v, uint2& h, uint2& l) {
    __nv_bfloat162 h0 = __floats2bfloat162_rn(v.x, v.y);
    __nv_bfloat162 h1 = __floats2bfloat162_rn(v.z, v.w);
    float2 f0 = __bfloat1622float2(h0);
    float2 f1 = __bfloat1622float2(h1);
    __nv_bfloat162 l0 = __floats2bfloat162_rn(v.x - f0.x, v.y - f0.y);
    __nv_bfloat162 l1 = __floats2bfloat162_rn(v.z - f1.x, v.w - f1.y);
    h.x = *(uint32_t*)&h0; h.y = *(uint32_t*)&h1;
    l.x = *(uint32_t*)&l0; l.y = *(uint32_t*)&l1;
}

// ---------------------------------------------------------------------------
// Kernel 1: split-bf16 mma.sync GEMM   C = x @ W^T + b
// 128x128 tile, 8 warps (2x4, each 64x32), double-buffered SW128 SMEM.
// ---------------------------------------------------------------------------
__global__ __launch_bounds__(256) void gemm_mma_kernel(
    const float* __restrict__ A,     // [M, K]
    const float* __restrict__ Bw,    // [N, K]
    const float* __restrict__ bias,  // [N]
    float* __restrict__ C)           // [M, N]
{
    constexpr int K = DINc;
    extern __shared__ char smem[];
    const uint32_t sbase = smem_u32(smem);
    const int tid    = threadIdx.x;
    const int lane   = tid & 31;
    const int wid    = tid >> 5;
    const int warp_m = wid >> 2;       // 0..1 -> M offset *64
    const int warp_n = wid & 3;        // 0..3 -> N offset *32
    const int bx = blockIdx.x, by = blockIdx.y;

    const float* Ag = A  + (size_t)(by * TM) * K;
    const float* Bg = Bw + (size_t)(bx * TN) * K;

    const int fo  = tid & 15;          // float4 index within 64-float row
    const int r0t = tid >> 4;          // base row (16 rows per iter step)
    const uint32_t sts_off = sw128((uint32_t)(r0t * 128 + fo * 8));

    float acc[4][4][4];
    #pragma unroll
    for (int i = 0; i < 4; i++)
        #pragma unroll
        for (int j = 0; j < 4; j++)
            #pragma unroll
            for (int k = 0; k < 4; k++) acc[i][j][k] = 0.0f;

    // ldmatrix per-thread row components (fixed per thread)
    const int a_row_base = warp_m * 64 + (lane & 15);      // + mt*16
    const int a_chunk    = (lane >> 4) << 4;               // 0 or 16 bytes
    const int b_row_base = warp_n * 32 + (((lane >> 4) & 1) << 3) + (lane & 7);  // + nt2*16
    const int b_chunk    = ((lane >> 3) & 1) << 4;

    auto kstep = [&](uint32_t stg, int ks) {
        uint32_t ah[4][4], al[4][4];
        #pragma unroll
        for (int mt = 0; mt < 4; mt++) {
            int row = a_row_base + mt * 16;
            uint32_t off = sw128((uint32_t)(row * 128 + ks * 32 + a_chunk));
            ldmx4(ah[mt], stg + 0 * TILE_B + off);
            ldmx4(al[mt], stg + 1 * TILE_B + off);
        }
        uint32_t bh[2][4], bl[2][4];
        #pragma unroll
        for (int nt2 = 0; nt2 < 2; nt2++) {
            int row = b_row_base + nt2 * 16;
            uint32_t off = sw128((uint32_t)(row * 128 + ks * 32 + b_chunk));
            ldmx4(bh[nt2], stg + 2 * TILE_B + off);
            ldmx4(bl[nt2], stg + 3 * TILE_B + off);
        }
        #pragma unroll
        for (int mt = 0; mt < 4; mt++)
            #pragma unroll
            for (int nt = 0; nt < 4; nt++) {
                float* c = acc[mt][nt];
                uint32_t b0h = bh[nt >> 1][(nt & 1) * 2], b1h = bh[nt >> 1][(nt & 1) * 2 + 1];
                uint32_t b0l = bl[nt >> 1][(nt & 1) * 2], b1l = bl[nt >> 1][(nt & 1) * 2 + 1];
                mma_bf16(c, ah[mt], b0h, b1h);   // hi*hi
                mma_bf16(c, al[mt], b0h, b1h);   // lo*hi
                mma_bf16(c, ah[mt], b0l, b1l);   // hi*lo
            }
    };

    // Prologue: chunk 0 -> stage 0
    {
        char* st = smem;
        #pragma unroll
        for (int it = 0; it < 8; it++) {
            int r = it * 16 + r0t;
            uint32_t off = sw128((uint32_t)(r * 128 + fo * 8));
            uint2 h, l;
            split4(*(const float4*)(Ag + (size_t)r * K + fo * 4), h, l);
            *(uint2*)(st + 0 * TILE_B + off) = h;
            *(uint2*)(st + 1 * TILE_B + off) = l;
            split4(*(const float4*)(Bg + (size_t)r * K + fo * 4), h, l);
            *(uint2*)(st + 2 * TILE_B + off) = h;
            *(uint2*)(st + 3 * TILE_B + off) = l;
        }
    }
    __syncthreads();

    for (int c = 0; c < NCHUNK; c++) {
        const uint32_t stg = sbase + (uint32_t)(c & 1) * STAGE_B;
        char* nst = smem + ((c + 1) & 1) * STAGE_B;
        const int kb = (c + 1) * KCF;
        const bool pf = (c + 1 < NCHUNK);

        float4 v[8];
        if (pf) {
            #pragma unroll
            for (int it = 0; it < 8; it++) {
                int r = it * 16 + r0t;
                v[it] = *(const float4*)(Ag + (size_t)r * K + kb + fo * 4);
            }
        }
        kstep(stg, 0);
        kstep(stg, 1);
        if (pf) {
            #pragma unroll
            for (int it = 0; it < 8; it++) {
                int r = it * 16 + r0t;
                uint32_t off = sw128((uint32_t)(r * 128 + fo * 8));
                uint2 h, l; split4(v[it], h, l);
                *(uint2*)(nst + 0 * TILE_B + off) = h;
                *(uint2*)(nst + 1 * TILE_B + off) = l;
            }
            #pragma unroll
            for (int it = 0; it < 8; it++) {
                int r = it * 16 + r0t;
                v[it] = *(const float4*)(Bg + (size_t)r * K + kb + fo * 4);
            }
        }
        kstep(stg, 2);
        kstep(stg, 3);
        if (pf) {
            #pragma unroll
            for (int it = 0; it < 8; it++) {
                int r = it * 16 + r0t;
                uint32_t off = sw128((uint32_t)(r * 128 + fo * 8));
                uint2 h, l; split4(v[it], h, l);
                *(uint2*)(nst + 2 * TILE_B + off) = h;
                *(uint2*)(nst + 3 * TILE_B + off) = l;
            }
        }
        __syncthreads();
    }

    // Epilogue: direct fp32 stores (each row segment = one full 32B sector)
    const int row0 = by * TM + warp_m * 64;
    const int col0 = bx * TN + warp_n * 32;
    #pragma unroll
    for (int mt = 0; mt < 4; mt++) {
        int r = row0 + mt * 16 + (lane >> 2);
        #pragma unroll
        for (int nt = 0; nt < 4; nt++) {
            int cc = col0 + nt * 8 + (lane & 3) * 2;
            float b0 = bias[cc], b1 = bias[cc + 1];
            float2 o0 = make_float2(acc[mt][nt][0] + b0, acc[mt][nt][1] + b1);
            float2 o1 = make_float2(acc[mt][nt][2] + b0, acc[mt][nt][3] + b1);
            *(float2*)(C + (size_t)r * Hc + cc)       = o0;
            *(float2*)(C + (size_t)(r + 8) * Hc + cc) = o1;
        }
    }
}

// ---------------------------------------------------------------------------
// Kernel 2: global abs-max over Hs = base[:, anchors, :E]
// ---------------------------------------------------------------------------
__global__ __launch_bounds__(256) void absmax_kernel(const float* __restrict__ C)
{
    __shared__ float red[256];
    float m = 0.0f;
    for (int i = threadIdx.x; i < Bc * NANCH * Ec; i += 256) {
        int b    = i >> 12;
        int rest = i & 4095;
        int a    = rest >> 3;
        int e    = rest & 7;
        int t    = a * 4 + 3;
        float v  = C[((size_t)(b * Tc + t)) * Hc + e];
        m = fmaxf(m, fabsf(v));
    }
    red[threadIdx.x] = m;
    __syncthreads();
    for (int s = 128; s > 0; s >>= 1) {
        if (threadIdx.x < s)
            red[threadIdx.x] = fmaxf(red[threadIdx.x], red[threadIdx.x + s]);
        __syncthreads();
    }
    if (threadIdx.x == 0) g_scale = fmaxf(red[0], 1e-6f);
}

// ---------------------------------------------------------------------------
// Kernel 3: softmax / top-2 soft mask / w @ LiMEs -> g_pmix
// ---------------------------------------------------------------------------
__global__ __launch_bounds__(256) void pmix_kernel(
    const float* __restrict__ C, const float* __restrict__ L)
{
    __shared__ float sL[Ec * RANKc];
    for (int i = threadIdx.x; i < Ec * RANKc; i += 256) sL[i] = L[i];
    __syncthreads();

    int idx = blockIdx.x * 256 + threadIdx.x;
    int b   = idx >> 9;
    int a   = idx & (NANCH - 1);
    int t   = a * 4 + 3;
    const float* h = C + ((size_t)(b * Tc + t)) * Hc;

    float inv_scale = 1.0f / g_scale;

    float l[Ec], lmax = -1e30f;
    #pragma unroll
    for (int e = 0; e < Ec; e++) {
        l[e] = h[e] * inv_scale;
        lmax = fmaxf(lmax, l[e]);
    }
    float p[Ec], s = 0.0f;
    #pragma unroll
    for (int e = 0; e < Ec; e++) { p[e] = expf(l[e] - lmax); s += p[e]; }
    float invs = 1.0f / s;
    #pragma unroll
    for (int e = 0; e < Ec; e++) p[e] *= invs;

    float m1 = -1e30f, m2 = -1e30f;
    #pragma unroll
    for (int e = 0; e < Ec; e++) {
        float v = p[e];
        if (v > m1) { m2 = m1; m1 = v; }
        else if (v > m2) { m2 = v; }
    }
    float w[Ec], ws = 0.0f;
    #pragma unroll
    for (int e = 0; e < Ec; e++) {
        float mask = 1.0f / (1.0f + expf(-(p[e] - m2) * 2.0f));
        w[e] = p[e] * mask;
        ws  += w[e];
    }
    float invws = 1.0f / (ws + 1e-9f);

    float* out = g_pmix + (size_t)idx * RANKc;
    #pragma unroll 8
    for (int r = 0; r < RANKc; r++) {
        float acc = 0.0f;
        #pragma unroll
        for (int e = 0; e < Ec; e++) acc += w[e] * sL[e * RANKc + r];
        out[r] = acc * invws;
    }
}

// ---------------------------------------------------------------------------
// Kernel 4: out[..., :RANK] *= (1 + SCALING * p_mix_full)
// ---------------------------------------------------------------------------
__global__ __launch_bounds__(256) void apply_kernel(float* __restrict__ C)
{
    int idx = blockIdx.x * blockDim.x + threadIdx.x;
    int r4  = idx & 15;
    int tg  = idx >> 4;
    int t   = tg & (Tc - 1);
    int b   = tg >> 11;
    int a   = t >> 2;

    const float4 p = ((const float4*)g_pmix)[((b << 9) + a) * 16 + r4];
    float4* cp = (float4*)(C + (size_t)tg * Hc) + r4;
    float4 v = *cp;
    v.x *= 1.0f + SCALING * p.x;
    v.y *= 1.0f + SCALING * p.y;
    v.z *= 1.0f + SCALING * p.z;
    v.w *= 1.0f + SCALING * p.w;
    *cp = v;
}

// ---------------------------------------------------------------------------
extern "C" void kernel_launch(void* const* d_in, const int* in_sizes, int n_in,
                              void* d_out, int out_size)
{
    const float* x = (const float*)d_in[0];
    const float* W = (const float*)d_in[1];
    const float* b = (const float*)d_in[2];
    const float* L = (const float*)d_in[3];
    float* out = (float*)d_out;

    cudaFuncSetAttribute(gemm_mma_kernel,
                         cudaFuncAttributeMaxDynamicSharedMemorySize, SMEM_TOTAL);

    dim3 grid(Hc / TN, (Bc * Tc) / TM);   // (16, 64)
    gemm_mma_kernel<<<grid, 256, SMEM_TOTAL>>>(x, W, b, out);
    absmax_kernel<<<1, 256>>>(out);
    pmix_kernel<<<(Bc * NANCH) / 256, 256>>>(out, L);
    apply_kernel<<<(Bc * Tc * 16) / 256, 256>>>(out);
}